// round 12
// baseline (speedup 1.0000x reference)
#include <cuda_runtime.h>
#include <cuda_fp16.h>
#include <math.h>

#define MAX_NODES 50000
#define MAX_EDGES 1500000
#define FEAT 128
#define SCAN_BLK 256
#define MAX_SCAN_BLOCKS 256   // ceil(50000/256)=196

// Scratch (device globals; allocation-free rule).
// g_deg is SELF-CLEANING: zero-initialized at module load, and the fused
// gather+gemm kernel re-zeroes every entry it reads, so it is zero at the
// start of every kernel_launch execution (incl. graph replays).
__device__ __half g_xh[MAX_NODES * FEAT];     // fp16 copy of x
__device__ __half g_wt[FEAT * FEAT];          // fp16 W^T  (wt[n][k] = W[k][n])
__device__ int    g_deg[MAX_NODES];
__device__ int    g_rowstart[MAX_NODES];
__device__ int    g_writeptr[MAX_NODES];
__device__ int    g_blocksum[MAX_SCAN_BLOCKS];
__device__ uint2  g_rec[MAX_EDGES];           // {sender, weight-bits}

// ---------------------------------------------------------------------------
// 1) prep+hist: x -> fp16, W -> fp16 transpose, receiver histogram.
//    deg is already zero on entry (self-cleaning invariant).
// ---------------------------------------------------------------------------
__global__ void prep_hist_kernel(const float* __restrict__ x,
                                 const float* __restrict__ W,
                                 const int* __restrict__ ei,
                                 __half* __restrict__ xh,
                                 __half* __restrict__ wt,
                                 int* __restrict__ deg,
                                 int n8, int E, int n_nodes) {
    int i = blockIdx.x * blockDim.x + threadIdx.x;
    if (i < FEAT * FEAT) {
        int n = i / FEAT, k = i % FEAT;
        wt[n * FEAT + k] = __float2half(W[k * FEAT + n]);
    }
    if (i < n8) {
        const float4* x4 = (const float4*)x;
        float4 a = x4[2 * i];
        float4 b = x4[2 * i + 1];
        __half2 h0 = __floats2half2_rn(a.x, a.y);
        __half2 h1 = __floats2half2_rn(a.z, a.w);
        __half2 h2 = __floats2half2_rn(b.x, b.y);
        __half2 h3 = __floats2half2_rn(b.z, b.w);
        uint4 o;
        o.x = *(unsigned*)&h0; o.y = *(unsigned*)&h1;
        o.z = *(unsigned*)&h2; o.w = *(unsigned*)&h3;
        ((uint4*)xh)[i] = o;
    }
    if (i < E) {
        int r = ei[E + i];
        r = min(max(r, 0), n_nodes - 1);
        atomicAdd(deg + r, 1);    // no return use -> REDG
    }
}

// ---------------------------------------------------------------------------
// 2) decoupled scan (all shfls with full-warp activity)
// ---------------------------------------------------------------------------
__device__ __forceinline__ int warp_incl_scan(int v, int lane) {
#pragma unroll
    for (int off = 1; off < 32; off <<= 1) {
        int u = __shfl_up_sync(0xffffffffu, v, off);
        if (lane >= off) v += u;
    }
    return v;
}

__global__ void scan_reduce_kernel(const int* __restrict__ deg,
                                   int* __restrict__ blocksum, int n) {
    __shared__ int warpsum[SCAN_BLK / 32];
    int t = threadIdx.x;
    int idx = blockIdx.x * SCAN_BLK + t;
    int v = (idx < n) ? deg[idx] : 0;
#pragma unroll
    for (int off = 16; off > 0; off >>= 1)
        v += __shfl_down_sync(0xffffffffu, v, off);
    if ((t & 31) == 0) warpsum[t >> 5] = v;
    __syncthreads();
    if (t < 32) {
        int s = (t < SCAN_BLK / 32) ? warpsum[t] : 0;
#pragma unroll
        for (int off = 16; off > 0; off >>= 1)
            s += __shfl_down_sync(0xffffffffu, s, off);
        if (t == 0) blocksum[blockIdx.x] = s;
    }
}

__global__ void scan_top_kernel(int* __restrict__ blocksum, int nb) {
    __shared__ int sh[SCAN_BLK / 32];
    int t = threadIdx.x;
    int lane = t & 31;
    int w = t >> 5;
    int v = (t < nb) ? blocksum[t] : 0;
    int incl = warp_incl_scan(v, lane);
    if (lane == 31) sh[w] = incl;
    __syncthreads();
    if (t < 32) {
        int s = (t < SCAN_BLK / 32) ? sh[t] : 0;
        int si = warp_incl_scan(s, t);
        if (t < SCAN_BLK / 32) sh[t] = si - s;
    }
    __syncthreads();
    if (t < nb) blocksum[t] = incl - v + sh[w];
}

__global__ void scan_final_kernel(const int* __restrict__ deg,
                                  const int* __restrict__ blocksum,
                                  int* __restrict__ rowstart,
                                  int* __restrict__ writeptr, int n) {
    __shared__ int sh[SCAN_BLK / 32];
    int t = threadIdx.x;
    int lane = t & 31;
    int w = t >> 5;
    int idx = blockIdx.x * SCAN_BLK + t;
    int v = (idx < n) ? deg[idx] : 0;
    int incl = warp_incl_scan(v, lane);
    if (lane == 31) sh[w] = incl;
    __syncthreads();
    if (t < 32) {
        int s = (t < SCAN_BLK / 32) ? sh[t] : 0;
        int si = warp_incl_scan(s, t);
        if (t < SCAN_BLK / 32) sh[t] = si - s;
    }
    __syncthreads();
    if (idx < n) {
        int start = blocksum[blockIdx.x] + sh[w] + incl - v;
        rowstart[idx] = start;
        writeptr[idx] = start;
    }
}

// ---------------------------------------------------------------------------
// 3) scatter: thread t owns CONTIGUOUS edges 8t..8t+7, vector loads,
//    8 in-flight atomic returns.
// ---------------------------------------------------------------------------
__global__ void scatter_kernel(const int* __restrict__ ei,
                               const float* __restrict__ elen,
                               const float* __restrict__ log_scale_p,
                               const float* __restrict__ fw_p,
                               const float* __restrict__ fb_p,
                               int* __restrict__ writeptr,
                               uint2* __restrict__ rec,
                               int E, int n_nodes) {
    int t = blockIdx.x * blockDim.x + threadIdx.x;
    int e0 = t * 8;
    if (e0 >= E) return;

    float scale = expf(log_scale_p[0]);
    float inv_s = 1.f / (scale + 1e-6f);
    float fw = fw_p[0];
    float fb = fb_p[0];

    int   s[8], r[8];
    float len[8];
    int   cnt;
    if (e0 + 8 <= E && (E & 3) == 0) {
        int4 sv0 = *(const int4*)(ei + e0);
        int4 sv1 = *(const int4*)(ei + e0 + 4);
        int4 rv0 = *(const int4*)(ei + E + e0);
        int4 rv1 = *(const int4*)(ei + E + e0 + 4);
        float4 lv0 = *(const float4*)(elen + e0);
        float4 lv1 = *(const float4*)(elen + e0 + 4);
        s[0]=sv0.x; s[1]=sv0.y; s[2]=sv0.z; s[3]=sv0.w;
        s[4]=sv1.x; s[5]=sv1.y; s[6]=sv1.z; s[7]=sv1.w;
        r[0]=rv0.x; r[1]=rv0.y; r[2]=rv0.z; r[3]=rv0.w;
        r[4]=rv1.x; r[5]=rv1.y; r[6]=rv1.z; r[7]=rv1.w;
        len[0]=lv0.x; len[1]=lv0.y; len[2]=lv0.z; len[3]=lv0.w;
        len[4]=lv1.x; len[5]=lv1.y; len[6]=lv1.z; len[7]=lv1.w;
        cnt = 8;
    } else {
        cnt = min(8, E - e0);
        for (int u = 0; u < cnt; u++) {
            s[u]   = ei[e0 + u];
            r[u]   = ei[E + e0 + u];
            len[u] = elen[e0 + u];
        }
    }

    float w[8];
    int   pos[8];
#pragma unroll
    for (int u = 0; u < 8; u++) {
        if (u < cnt) {
            s[u] = min(max(s[u], 0), n_nodes - 1);
            r[u] = min(max(r[u], 0), n_nodes - 1);
            float tt = fmaxf(len[u] * inv_s, 0.f);
            float d = expf(-tt * tt);
            float g = 1.f / (1.f + expf(-(len[u] * fw + fb)));
            float ww = d * g;
            if (!(ww > -3.0e38f && ww < 3.0e38f)) ww = 0.f;
            w[u] = ww;
        }
    }
#pragma unroll
    for (int u = 0; u < 8; u++) {
        if (u < cnt) pos[u] = atomicAdd(writeptr + r[u], 1);
    }
#pragma unroll
    for (int u = 0; u < 8; u++) {
        if (u < cnt) rec[pos[u]] = make_uint2((unsigned)s[u],
                                              __float_as_uint(w[u]));
    }
}

// ---------------------------------------------------------------------------
// 4) fused gather + tensor-core GEMM + residual.
//    Block = 128 nodes, 8 warps. Each warp gathers 16 nodes (fp32 accum,
//    fp16 into the smem A tile), zeroes deg[node] after use (self-clean),
//    then the block does out = x + A @ W via mma.sync.m16n8k16.
// ---------------------------------------------------------------------------
#define GM 128
#define PITCH 136   // halves; 272 B, multiple of 16 B

__global__ void gather_gemm_kernel(const float* __restrict__ x,
                                   const __half* __restrict__ xh,
                                   const __half* __restrict__ wt,
                                   const uint2* __restrict__ rec,
                                   const int* __restrict__ rowstart,
                                   int* __restrict__ deg,
                                   float* __restrict__ out,
                                   int n_nodes) {
    extern __shared__ __half sh[];
    __half* sA = sh;                  // GM rows * PITCH
    __half* sB = sh + GM * PITCH;     // FEAT rows * PITCH (Wt: [n][k])

    int tid = threadIdx.x;
    int lane = tid & 31;
    int wid = tid >> 5;               // 0..7
    int row0 = blockIdx.x * GM;

    // stage Wt
    for (int i = tid; i < FEAT * 16; i += 256) {
        int r = i >> 4;
        int c = i & 15;
        uint4 v = ((const uint4*)(wt + r * FEAT))[c];
        *(uint4*)(sB + r * PITCH + c * 8) = v;
    }

    // gather phase: warp w owns rows w*16 .. w*16+15
    for (int j = 0; j < 16; j++) {
        int r_local = wid * 16 + j;
        int node = row0 + r_local;              // warp-uniform
        float4 acc = make_float4(0.f, 0.f, 0.f, 0.f);
        int d = 0;
        if (node < n_nodes) {                   // warp-uniform branch
            int base = rowstart[node];
            d = deg[node];
            for (int j0 = 0; j0 < d; j0 += 32) {
                int n = min(32, d - j0);
                uint2 rv = make_uint2(0u, 0u);
                if (lane < n) rv = rec[base + j0 + lane];
                for (int k = 0; k < n; k += 8) {
                    int   si[8];
                    float wi[8];
#pragma unroll
                    for (int u = 0; u < 8; u++) {
                        si[u] = __shfl_sync(0xffffffffu, (int)rv.x, k + u);
                        wi[u] = __uint_as_float(
                            __shfl_sync(0xffffffffu, rv.y, k + u));
                    }
                    uint2 hv[8];
#pragma unroll
                    for (int u = 0; u < 8; u++) {
                        hv[u] = ((const uint2*)(xh +
                                 (size_t)si[u] * FEAT))[lane];
                    }
#pragma unroll
                    for (int u = 0; u < 8; u++) {
                        float2 f0 = __half22float2(*(__half2*)&hv[u].x);
                        float2 f1 = __half22float2(*(__half2*)&hv[u].y);
                        acc.x = fmaf(wi[u], f0.x, acc.x);
                        acc.y = fmaf(wi[u], f0.y, acc.y);
                        acc.z = fmaf(wi[u], f1.x, acc.z);
                        acc.w = fmaf(wi[u], f1.y, acc.w);
                    }
                }
            }
        }
        float inv = 1.f / fmaxf((float)d, 1.f);
        __half2 h0 = __floats2half2_rn(acc.x * inv, acc.y * inv);
        __half2 h1 = __floats2half2_rn(acc.z * inv, acc.w * inv);
        uint2 o;
        o.x = *(unsigned*)&h0; o.y = *(unsigned*)&h1;
        *(uint2*)(sA + r_local * PITCH + lane * 4) = o;
        // self-clean AFTER the warp-level read of deg[node]
        if (lane == 0 && node < n_nodes) deg[node] = 0;
    }
    __syncthreads();

    // MMA phase
    int warpRow = wid * 16;
    int g = lane >> 2;        // 0..7
    int tg = lane & 3;        // 0..3

    unsigned af[8][4];
    {
        int arow = warpRow + (lane & 15);
        int acolH = (lane >> 4) << 3;   // 0 or 8 halves
#pragma unroll
        for (int kk = 0; kk < 8; kk++) {
            unsigned addr = (unsigned)__cvta_generic_to_shared(
                sA + arow * PITCH + kk * 16 + acolH);
            asm volatile(
                "ldmatrix.sync.aligned.m8n8.x4.shared.b16 {%0,%1,%2,%3}, [%4];"
                : "=r"(af[kk][0]), "=r"(af[kk][1]),
                  "=r"(af[kk][2]), "=r"(af[kk][3])
                : "r"(addr));
        }
    }

    int r1 = row0 + warpRow + g;
    int r2 = r1 + 8;

#pragma unroll
    for (int n = 0; n < 16; n += 2) {
        float c0[4] = {0.f, 0.f, 0.f, 0.f};
        float c1[4] = {0.f, 0.f, 0.f, 0.f};
#pragma unroll
        for (int kk = 0; kk < 8; kk++) {
            int brow0 = (n << 3) + (lane & 7);
            int bcol  = (kk << 4) + (((lane >> 3) & 1) << 3);
            unsigned baddr0 = (unsigned)__cvta_generic_to_shared(
                sB + brow0 * PITCH + bcol);
            unsigned baddr1 = (unsigned)__cvta_generic_to_shared(
                sB + (brow0 + 8) * PITCH + bcol);
            unsigned b0, b1, b2, b3;
            asm volatile(
                "ldmatrix.sync.aligned.m8n8.x2.shared.b16 {%0,%1}, [%2];"
                : "=r"(b0), "=r"(b1) : "r"(baddr0));
            asm volatile(
                "ldmatrix.sync.aligned.m8n8.x2.shared.b16 {%0,%1}, [%2];"
                : "=r"(b2), "=r"(b3) : "r"(baddr1));
            asm volatile(
                "mma.sync.aligned.m16n8k16.row.col.f32.f16.f16.f32 "
                "{%0,%1,%2,%3}, {%4,%5,%6,%7}, {%8,%9}, {%0,%1,%2,%3};"
                : "+f"(c0[0]), "+f"(c0[1]), "+f"(c0[2]), "+f"(c0[3])
                : "r"(af[kk][0]), "r"(af[kk][1]), "r"(af[kk][2]), "r"(af[kk][3]),
                  "r"(b0), "r"(b1));
            asm volatile(
                "mma.sync.aligned.m16n8k16.row.col.f32.f16.f16.f32 "
                "{%0,%1,%2,%3}, {%4,%5,%6,%7}, {%8,%9}, {%0,%1,%2,%3};"
                : "+f"(c1[0]), "+f"(c1[1]), "+f"(c1[2]), "+f"(c1[3])
                : "r"(af[kk][0]), "r"(af[kk][1]), "r"(af[kk][2]), "r"(af[kk][3]),
                  "r"(b2), "r"(b3));
        }
        int col0 = (n << 3) + (tg << 1);
        int col1 = col0 + 8;
        if (r1 < n_nodes) {
            float2 xv0 = *(const float2*)(x + (size_t)r1 * FEAT + col0);
            float2 xv1 = *(const float2*)(x + (size_t)r1 * FEAT + col1);
            *(float2*)(out + (size_t)r1 * FEAT + col0) =
                make_float2(c0[0] + xv0.x, c0[1] + xv0.y);
            *(float2*)(out + (size_t)r1 * FEAT + col1) =
                make_float2(c1[0] + xv1.x, c1[1] + xv1.y);
        }
        if (r2 < n_nodes) {
            float2 xv0 = *(const float2*)(x + (size_t)r2 * FEAT + col0);
            float2 xv1 = *(const float2*)(x + (size_t)r2 * FEAT + col1);
            *(float2*)(out + (size_t)r2 * FEAT + col0) =
                make_float2(c0[2] + xv0.x, c0[3] + xv0.y);
            *(float2*)(out + (size_t)r2 * FEAT + col1) =
                make_float2(c1[2] + xv1.x, c1[3] + xv1.y);
        }
    }
}

// ---------------------------------------------------------------------------
extern "C" void kernel_launch(void* const* d_in, const int* in_sizes, int n_in,
                              void* d_out, int out_size) {
    const float* x    = (const float*)d_in[0];
    const int*   ei   = (const int*)d_in[1];
    const float* elen = (const float*)d_in[2];
    const float* W    = (const float*)d_in[3];
    const float* lsc  = (const float*)d_in[4];
    const float* fw   = (const float*)d_in[5];
    const float* fb   = (const float*)d_in[6];
    float* out = (float*)d_out;

    int n_nodes = in_sizes[0] / FEAT;
    int E       = in_sizes[2];
    if (E > MAX_EDGES) E = MAX_EDGES;

    __half* xh;       cudaGetSymbolAddress((void**)&xh, g_xh);
    __half* wt;       cudaGetSymbolAddress((void**)&wt, g_wt);
    int*    deg;      cudaGetSymbolAddress((void**)&deg, g_deg);
    int*    rowstart; cudaGetSymbolAddress((void**)&rowstart, g_rowstart);
    int*    writeptr; cudaGetSymbolAddress((void**)&writeptr, g_writeptr);
    int*    blocksum; cudaGetSymbolAddress((void**)&blocksum, g_blocksum);
    uint2*  rec;      cudaGetSymbolAddress((void**)&rec, g_rec);

    // 1) fused prep + histogram (deg is zero on entry: self-cleaning)
    {
        int n8 = n_nodes * FEAT / 8;
        prep_hist_kernel<<<(E + 255) / 256, 256>>>(x, W, ei, xh, wt, deg,
                                                   n8, E, n_nodes);
    }

    // 2) decoupled prefix scan -> rowstart / writeptr
    {
        int nb = (n_nodes + SCAN_BLK - 1) / SCAN_BLK;   // 196
        scan_reduce_kernel<<<nb, SCAN_BLK>>>(deg, blocksum, n_nodes);
        scan_top_kernel<<<1, SCAN_BLK>>>(blocksum, nb);
        scan_final_kernel<<<nb, SCAN_BLK>>>(deg, blocksum, rowstart,
                                            writeptr, n_nodes);
    }

    // 3) bucket scatter, 8 contiguous edges per thread
    {
        int T = (E + 7) / 8;
        scatter_kernel<<<(T + 255) / 256, 256>>>(ei, elen, lsc, fw, fb,
                                                 writeptr, rec, E, n_nodes);
    }

    // 4) fused gather + GEMM + residual (also self-cleans deg)
    {
        int smem = (GM * PITCH + FEAT * PITCH) * (int)sizeof(__half); // ~68 KB
        cudaFuncSetAttribute(gather_gemm_kernel,
                             cudaFuncAttributeMaxDynamicSharedMemorySize, smem);
        gather_gemm_kernel<<<(n_nodes + GM - 1) / GM, 256, smem>>>(
            x, xh, wt, rec, rowstart, deg, out, n_nodes);
    }
}

// round 14
// speedup vs baseline: 1.0224x; 1.0224x over previous
#include <cuda_runtime.h>
#include <cuda_fp16.h>
#include <math.h>

#define MAX_NODES 50000
#define MAX_EDGES 1500000
#define FEAT 128
#define SCAN_BLK 256
#define MAX_SCAN_BLOCKS 256   // ceil(50000/256)=196

// Scratch (device globals; allocation-free rule).
// g_deg is SELF-CLEANING: zero at module load; the gather kernel re-zeroes
// every entry after its (single-owner) read, so deg is zero at the start of
// every kernel_launch execution, including graph replays.
__device__ __half g_aggh[MAX_NODES * FEAT];   // fp16 normalized aggregate
__device__ __half g_xh[MAX_NODES * FEAT];     // fp16 copy of x
__device__ __half g_wt[FEAT * FEAT];          // fp16 W^T (wt[n][k] = W[k][n])
__device__ int    g_deg[MAX_NODES];
__device__ int    g_rowstart[MAX_NODES];
__device__ int    g_writeptr[MAX_NODES];
__device__ int    g_blocksum[MAX_SCAN_BLOCKS];
__device__ uint2  g_rec[MAX_EDGES];           // {sender, weight-bits}

// ---------------------------------------------------------------------------
// 1) prep+hist: x -> fp16, W -> fp16 transpose, receiver histogram.
//    deg is already zero on entry (self-cleaning invariant).
// ---------------------------------------------------------------------------
__global__ void prep_hist_kernel(const float* __restrict__ x,
                                 const float* __restrict__ W,
                                 const int* __restrict__ ei,
                                 __half* __restrict__ xh,
                                 __half* __restrict__ wt,
                                 int* __restrict__ deg,
                                 int n8, int E, int n_nodes) {
    int i = blockIdx.x * blockDim.x + threadIdx.x;
    if (i < FEAT * FEAT) {
        int n = i / FEAT, k = i % FEAT;
        wt[n * FEAT + k] = __float2half(W[k * FEAT + n]);
    }
    if (i < n8) {
        const float4* x4 = (const float4*)x;
        float4 a = x4[2 * i];
        float4 b = x4[2 * i + 1];
        __half2 h0 = __floats2half2_rn(a.x, a.y);
        __half2 h1 = __floats2half2_rn(a.z, a.w);
        __half2 h2 = __floats2half2_rn(b.x, b.y);
        __half2 h3 = __floats2half2_rn(b.z, b.w);
        uint4 o;
        o.x = *(unsigned*)&h0; o.y = *(unsigned*)&h1;
        o.z = *(unsigned*)&h2; o.w = *(unsigned*)&h3;
        ((uint4*)xh)[i] = o;
    }
    if (i < E) {
        int r = ei[E + i];
        r = min(max(r, 0), n_nodes - 1);
        atomicAdd(deg + r, 1);    // no return use -> REDG
    }
}

// ---------------------------------------------------------------------------
// 2) decoupled scan (all shfls with full-warp activity)
// ---------------------------------------------------------------------------
__device__ __forceinline__ int warp_incl_scan(int v, int lane) {
#pragma unroll
    for (int off = 1; off < 32; off <<= 1) {
        int u = __shfl_up_sync(0xffffffffu, v, off);
        if (lane >= off) v += u;
    }
    return v;
}

__global__ void scan_reduce_kernel(const int* __restrict__ deg,
                                   int* __restrict__ blocksum, int n) {
    __shared__ int warpsum[SCAN_BLK / 32];
    int t = threadIdx.x;
    int idx = blockIdx.x * SCAN_BLK + t;
    int v = (idx < n) ? deg[idx] : 0;
#pragma unroll
    for (int off = 16; off > 0; off >>= 1)
        v += __shfl_down_sync(0xffffffffu, v, off);
    if ((t & 31) == 0) warpsum[t >> 5] = v;
    __syncthreads();
    if (t < 32) {
        int s = (t < SCAN_BLK / 32) ? warpsum[t] : 0;
#pragma unroll
        for (int off = 16; off > 0; off >>= 1)
            s += __shfl_down_sync(0xffffffffu, s, off);
        if (t == 0) blocksum[blockIdx.x] = s;
    }
}

__global__ void scan_top_kernel(int* __restrict__ blocksum, int nb) {
    __shared__ int sh[SCAN_BLK / 32];
    int t = threadIdx.x;
    int lane = t & 31;
    int w = t >> 5;
    int v = (t < nb) ? blocksum[t] : 0;
    int incl = warp_incl_scan(v, lane);
    if (lane == 31) sh[w] = incl;
    __syncthreads();
    if (t < 32) {
        int s = (t < SCAN_BLK / 32) ? sh[t] : 0;
        int si = warp_incl_scan(s, t);
        if (t < SCAN_BLK / 32) sh[t] = si - s;
    }
    __syncthreads();
    if (t < nb) blocksum[t] = incl - v + sh[w];
}

__global__ void scan_final_kernel(const int* __restrict__ deg,
                                  const int* __restrict__ blocksum,
                                  int* __restrict__ rowstart,
                                  int* __restrict__ writeptr, int n) {
    __shared__ int sh[SCAN_BLK / 32];
    int t = threadIdx.x;
    int lane = t & 31;
    int w = t >> 5;
    int idx = blockIdx.x * SCAN_BLK + t;
    int v = (idx < n) ? deg[idx] : 0;
    int incl = warp_incl_scan(v, lane);
    if (lane == 31) sh[w] = incl;
    __syncthreads();
    if (t < 32) {
        int s = (t < SCAN_BLK / 32) ? sh[t] : 0;
        int si = warp_incl_scan(s, t);
        if (t < SCAN_BLK / 32) sh[t] = si - s;
    }
    __syncthreads();
    if (idx < n) {
        int start = blocksum[blockIdx.x] + sh[w] + incl - v;
        rowstart[idx] = start;
        writeptr[idx] = start;
    }
}

// ---------------------------------------------------------------------------
// 3) scatter: thread t owns CONTIGUOUS edges 8t..8t+7, vector loads,
//    8 in-flight atomic returns.
// ---------------------------------------------------------------------------
__global__ void scatter_kernel(const int* __restrict__ ei,
                               const float* __restrict__ elen,
                               const float* __restrict__ log_scale_p,
                               const float* __restrict__ fw_p,
                               const float* __restrict__ fb_p,
                               int* __restrict__ writeptr,
                               uint2* __restrict__ rec,
                               int E, int n_nodes) {
    int t = blockIdx.x * blockDim.x + threadIdx.x;
    int e0 = t * 8;
    if (e0 >= E) return;

    float scale = expf(log_scale_p[0]);
    float inv_s = 1.f / (scale + 1e-6f);
    float fw = fw_p[0];
    float fb = fb_p[0];

    int   s[8], r[8];
    float len[8];
    int   cnt;
    if (e0 + 8 <= E && (E & 3) == 0) {
        int4 sv0 = *(const int4*)(ei + e0);
        int4 sv1 = *(const int4*)(ei + e0 + 4);
        int4 rv0 = *(const int4*)(ei + E + e0);
        int4 rv1 = *(const int4*)(ei + E + e0 + 4);
        float4 lv0 = *(const float4*)(elen + e0);
        float4 lv1 = *(const float4*)(elen + e0 + 4);
        s[0]=sv0.x; s[1]=sv0.y; s[2]=sv0.z; s[3]=sv0.w;
        s[4]=sv1.x; s[5]=sv1.y; s[6]=sv1.z; s[7]=sv1.w;
        r[0]=rv0.x; r[1]=rv0.y; r[2]=rv0.z; r[3]=rv0.w;
        r[4]=rv1.x; r[5]=rv1.y; r[6]=rv1.z; r[7]=rv1.w;
        len[0]=lv0.x; len[1]=lv0.y; len[2]=lv0.z; len[3]=lv0.w;
        len[4]=lv1.x; len[5]=lv1.y; len[6]=lv1.z; len[7]=lv1.w;
        cnt = 8;
    } else {
        cnt = min(8, E - e0);
        for (int u = 0; u < cnt; u++) {
            s[u]   = ei[e0 + u];
            r[u]   = ei[E + e0 + u];
            len[u] = elen[e0 + u];
        }
    }

    float w[8];
    int   pos[8];
#pragma unroll
    for (int u = 0; u < 8; u++) {
        if (u < cnt) {
            s[u] = min(max(s[u], 0), n_nodes - 1);
            r[u] = min(max(r[u], 0), n_nodes - 1);
            float tt = fmaxf(len[u] * inv_s, 0.f);
            float d = expf(-tt * tt);
            float g = 1.f / (1.f + expf(-(len[u] * fw + fb)));
            float ww = d * g;
            if (!(ww > -3.0e38f && ww < 3.0e38f)) ww = 0.f;
            w[u] = ww;
        }
    }
#pragma unroll
    for (int u = 0; u < 8; u++) {
        if (u < cnt) pos[u] = atomicAdd(writeptr + r[u], 1);
    }
#pragma unroll
    for (int u = 0; u < 8; u++) {
        if (u < cnt) rec[pos[u]] = make_uint2((unsigned)s[u],
                                              __float_as_uint(w[u]));
    }
}

// ---------------------------------------------------------------------------
// 4) gather (fp16 x): warp per node, no smem -> full occupancy. fp32 accum,
//    writes NORMALIZED agg as fp16, then self-cleans deg[node].
// ---------------------------------------------------------------------------
__global__ void gather_kernel(const __half* __restrict__ xh,
                              const uint2* __restrict__ rec,
                              const int* __restrict__ rowstart,
                              int* __restrict__ deg,
                              __half* __restrict__ aggh, int n_nodes) {
    int wid  = (blockIdx.x * blockDim.x + threadIdx.x) >> 5;
    int lane = threadIdx.x & 31;
    if (wid >= n_nodes) return;

    int base = rowstart[wid];
    int d    = deg[wid];
    float4 acc = make_float4(0.f, 0.f, 0.f, 0.f);

    for (int j0 = 0; j0 < d; j0 += 32) {
        int n = min(32, d - j0);
        uint2 rv = make_uint2(0u, 0u);
        if (lane < n) rv = rec[base + j0 + lane];

        for (int k = 0; k < n; k += 8) {
            int   si[8];
            float wi[8];
#pragma unroll
            for (int u = 0; u < 8; u++) {
                si[u] = __shfl_sync(0xffffffffu, (int)rv.x, k + u);
                wi[u] = __uint_as_float(__shfl_sync(0xffffffffu, rv.y, k + u));
            }
            uint2 hv[8];
#pragma unroll
            for (int u = 0; u < 8; u++) {
                hv[u] = ((const uint2*)(xh + (size_t)si[u] * FEAT))[lane];
            }
#pragma unroll
            for (int u = 0; u < 8; u++) {
                float2 f0 = __half22float2(*(__half2*)&hv[u].x);
                float2 f1 = __half22float2(*(__half2*)&hv[u].y);
                acc.x = fmaf(wi[u], f0.x, acc.x);
                acc.y = fmaf(wi[u], f0.y, acc.y);
                acc.z = fmaf(wi[u], f1.x, acc.z);
                acc.w = fmaf(wi[u], f1.y, acc.w);
            }
        }
    }

    float inv = 1.f / fmaxf((float)d, 1.f);
    __half2 h0 = __floats2half2_rn(acc.x * inv, acc.y * inv);
    __half2 h1 = __floats2half2_rn(acc.z * inv, acc.w * inv);
    uint2 o;
    o.x = *(unsigned*)&h0; o.y = *(unsigned*)&h1;
    ((uint2*)(aggh + (size_t)wid * FEAT))[lane] = o;

    if (lane == 0) deg[wid] = 0;   // self-clean after the read above
}

// ---------------------------------------------------------------------------
// 5) out = x + aggh @ W  via mma.sync.m16n8k16 (f16 in, f32 accum)
// ---------------------------------------------------------------------------
#define GM 128
#define PITCH 136   // halves; 272 B, multiple of 16 B

__global__ void gemm_kernel(const float* __restrict__ x,
                            const __half* __restrict__ wt,
                            const __half* __restrict__ aggh,
                            float* __restrict__ out,
                            int n_nodes) {
    extern __shared__ __half sh[];
    __half* sA = sh;                  // GM rows * PITCH
    __half* sB = sh + GM * PITCH;     // FEAT rows * PITCH (Wt: [n][k])

    int tid = threadIdx.x;
    int lane = tid & 31;
    int wid = tid >> 5;               // 0..7
    int row0 = blockIdx.x * GM;

    for (int i = tid; i < GM * 16; i += 256) {
        int r = i >> 4;
        int c = i & 15;
        uint4 v = make_uint4(0u, 0u, 0u, 0u);
        int row = row0 + r;
        if (row < n_nodes) {
            v = ((const uint4*)(aggh + (size_t)row * FEAT))[c];
        }
        *(uint4*)(sA + r * PITCH + c * 8) = v;
    }
    for (int i = tid; i < FEAT * 16; i += 256) {
        int r = i >> 4;
        int c = i & 15;
        uint4 v = ((const uint4*)(wt + r * FEAT))[c];
        *(uint4*)(sB + r * PITCH + c * 8) = v;
    }
    __syncthreads();

    int warpRow = wid * 16;
    int g = lane >> 2;        // 0..7
    int tg = lane & 3;        // 0..3

    unsigned af[8][4];
    {
        int arow = warpRow + (lane & 15);
        int acolH = (lane >> 4) << 3;   // 0 or 8 halves
#pragma unroll
        for (int kk = 0; kk < 8; kk++) {
            unsigned addr = (unsigned)__cvta_generic_to_shared(
                sA + arow * PITCH + kk * 16 + acolH);
            asm volatile(
                "ldmatrix.sync.aligned.m8n8.x4.shared.b16 {%0,%1,%2,%3}, [%4];"
                : "=r"(af[kk][0]), "=r"(af[kk][1]),
                  "=r"(af[kk][2]), "=r"(af[kk][3])
                : "r"(addr));
        }
    }

    int r1 = row0 + warpRow + g;
    int r2 = r1 + 8;

#pragma unroll
    for (int n = 0; n < 16; n += 2) {
        float c0[4] = {0.f, 0.f, 0.f, 0.f};
        float c1[4] = {0.f, 0.f, 0.f, 0.f};
#pragma unroll
        for (int kk = 0; kk < 8; kk++) {
            int brow0 = (n << 3) + (lane & 7);
            int bcol  = (kk << 4) + (((lane >> 3) & 1) << 3);
            unsigned baddr0 = (unsigned)__cvta_generic_to_shared(
                sB + brow0 * PITCH + bcol);
            unsigned baddr1 = (unsigned)__cvta_generic_to_shared(
                sB + (brow0 + 8) * PITCH + bcol);
            unsigned b0, b1, b2, b3;
            asm volatile(
                "ldmatrix.sync.aligned.m8n8.x2.shared.b16 {%0,%1}, [%2];"
                : "=r"(b0), "=r"(b1) : "r"(baddr0));
            asm volatile(
                "ldmatrix.sync.aligned.m8n8.x2.shared.b16 {%0,%1}, [%2];"
                : "=r"(b2), "=r"(b3) : "r"(baddr1));
            asm volatile(
                "mma.sync.aligned.m16n8k16.row.col.f32.f16.f16.f32 "
                "{%0,%1,%2,%3}, {%4,%5,%6,%7}, {%8,%9}, {%0,%1,%2,%3};"
                : "+f"(c0[0]), "+f"(c0[1]), "+f"(c0[2]), "+f"(c0[3])
                : "r"(af[kk][0]), "r"(af[kk][1]), "r"(af[kk][2]), "r"(af[kk][3]),
                  "r"(b0), "r"(b1));
            asm volatile(
                "mma.sync.aligned.m16n8k16.row.col.f32.f16.f16.f32 "
                "{%0,%1,%2,%3}, {%4,%5,%6,%7}, {%8,%9}, {%0,%1,%2,%3};"
                : "+f"(c1[0]), "+f"(c1[1]), "+f"(c1[2]), "+f"(c1[3])
                : "r"(af[kk][0]), "r"(af[kk][1]), "r"(af[kk][2]), "r"(af[kk][3]),
                  "r"(b2), "r"(b3));
        }
        int col0 = (n << 3) + (tg << 1);
        int col1 = col0 + 8;
        if (r1 < n_nodes) {
            float2 xv0 = *(const float2*)(x + (size_t)r1 * FEAT + col0);
            float2 xv1 = *(const float2*)(x + (size_t)r1 * FEAT + col1);
            *(float2*)(out + (size_t)r1 * FEAT + col0) =
                make_float2(c0[0] + xv0.x, c0[1] + xv0.y);
            *(float2*)(out + (size_t)r1 * FEAT + col1) =
                make_float2(c1[0] + xv1.x, c1[1] + xv1.y);
        }
        if (r2 < n_nodes) {
            float2 xv0 = *(const float2*)(x + (size_t)r2 * FEAT + col0);
            float2 xv1 = *(const float2*)(x + (size_t)r2 * FEAT + col1);
            *(float2*)(out + (size_t)r2 * FEAT + col0) =
                make_float2(c0[2] + xv0.x, c0[3] + xv0.y);
            *(float2*)(out + (size_t)r2 * FEAT + col1) =
                make_float2(c1[2] + xv1.x, c1[3] + xv1.y);
        }
    }
}

// ---------------------------------------------------------------------------
extern "C" void kernel_launch(void* const* d_in, const int* in_sizes, int n_in,
                              void* d_out, int out_size) {
    const float* x    = (const float*)d_in[0];
    const int*   ei   = (const int*)d_in[1];
    const float* elen = (const float*)d_in[2];
    const float* W    = (const float*)d_in[3];
    const float* lsc  = (const float*)d_in[4];
    const float* fw   = (const float*)d_in[5];
    const float* fb   = (const float*)d_in[6];
    float* out = (float*)d_out;

    int n_nodes = in_sizes[0] / FEAT;
    int E       = in_sizes[2];
    if (E > MAX_EDGES) E = MAX_EDGES;

    __half* aggh;     cudaGetSymbolAddress((void**)&aggh, g_aggh);
    __half* xh;       cudaGetSymbolAddress((void**)&xh, g_xh);
    __half* wt;       cudaGetSymbolAddress((void**)&wt, g_wt);
    int*    deg;      cudaGetSymbolAddress((void**)&deg, g_deg);
    int*    rowstart; cudaGetSymbolAddress((void**)&rowstart, g_rowstart);
    int*    writeptr; cudaGetSymbolAddress((void**)&writeptr, g_writeptr);
    int*    blocksum; cudaGetSymbolAddress((void**)&blocksum, g_blocksum);
    uint2*  rec;      cudaGetSymbolAddress((void**)&rec, g_rec);

    // 1) fused prep + histogram (deg is zero on entry: self-cleaning)
    {
        int n8 = n_nodes * FEAT / 8;
        prep_hist_kernel<<<(E + 255) / 256, 256>>>(x, W, ei, xh, wt, deg,
                                                   n8, E, n_nodes);
    }

    // 2) decoupled prefix scan -> rowstart / writeptr
    {
        int nb = (n_nodes + SCAN_BLK - 1) / SCAN_BLK;   // 196
        scan_reduce_kernel<<<nb, SCAN_BLK>>>(deg, blocksum, n_nodes);
        scan_top_kernel<<<1, SCAN_BLK>>>(blocksum, nb);
        scan_final_kernel<<<nb, SCAN_BLK>>>(deg, blocksum, rowstart,
                                            writeptr, n_nodes);
    }

    // 3) bucket scatter, 8 contiguous edges per thread
    {
        int T = (E + 7) / 8;
        scatter_kernel<<<(T + 255) / 256, 256>>>(ei, elen, lsc, fw, fb,
                                                 writeptr, rec, E, n_nodes);
    }

    // 4) gather (warp per node, full occupancy) -> fp16 agg; self-cleans deg
    {
        long long total = (long long)n_nodes * 32;
        int blocks = (int)((total + 255) / 256);
        gather_kernel<<<blocks, 256>>>(xh, rec, rowstart, deg, aggh, n_nodes);
    }

    // 5) tensor-core GEMM + residual
    {
        int smem = (GM * PITCH + FEAT * PITCH) * (int)sizeof(__half); // ~68 KB
        cudaFuncSetAttribute(gemm_kernel,
                             cudaFuncAttributeMaxDynamicSharedMemorySize, smem);
        gemm_kernel<<<(n_nodes + GM - 1) / GM, 256, smem>>>(x, wt, aggh, out,
                                                            n_nodes);
    }
}

// round 15
// speedup vs baseline: 1.0585x; 1.0354x over previous
#include <cuda_runtime.h>
#include <cuda_fp16.h>
#include <math.h>

#define MAX_NODES 50000
#define MAX_EDGES 1500000
#define FEAT 128
#define SCAN_BLK 256

// Scratch (device globals; allocation-free rule).
// g_deg is SELF-CLEANING: zero at module load; the gather kernel re-zeroes
// every entry after its (single-owner) read, so deg is zero at the start of
// every kernel_launch execution, including graph replays.
// g_alloc_ctr is reset by prep_hist_kernel (stream-ordered before the scan).
__device__ __half g_aggh[MAX_NODES * FEAT];   // fp16 normalized aggregate
__device__ __half g_xh[MAX_NODES * FEAT];     // fp16 copy of x
__device__ __half g_wt[FEAT * FEAT];          // fp16 W^T (wt[n][k] = W[k][n])
__device__ int    g_deg[MAX_NODES];
__device__ int    g_rowstart[MAX_NODES];
__device__ int    g_writeptr[MAX_NODES];
__device__ int    g_alloc_ctr;
__device__ uint2  g_rec[MAX_EDGES];           // {sender, weight-bits}

// ---------------------------------------------------------------------------
// 1) prep+hist: x -> fp16, W -> fp16 transpose, receiver histogram,
//    reset the bucket allocator. deg is already zero on entry.
// ---------------------------------------------------------------------------
__global__ void prep_hist_kernel(const float* __restrict__ x,
                                 const float* __restrict__ W,
                                 const int* __restrict__ ei,
                                 __half* __restrict__ xh,
                                 __half* __restrict__ wt,
                                 int* __restrict__ deg,
                                 int* __restrict__ alloc_ctr,
                                 int n8, int E, int n_nodes) {
    int i = blockIdx.x * blockDim.x + threadIdx.x;
    if (i == 0) *alloc_ctr = 0;
    if (i < FEAT * FEAT) {
        int n = i / FEAT, k = i % FEAT;
        wt[n * FEAT + k] = __float2half(W[k * FEAT + n]);
    }
    if (i < n8) {
        const float4* x4 = (const float4*)x;
        float4 a = x4[2 * i];
        float4 b = x4[2 * i + 1];
        __half2 h0 = __floats2half2_rn(a.x, a.y);
        __half2 h1 = __floats2half2_rn(a.z, a.w);
        __half2 h2 = __floats2half2_rn(b.x, b.y);
        __half2 h3 = __floats2half2_rn(b.z, b.w);
        uint4 o;
        o.x = *(unsigned*)&h0; o.y = *(unsigned*)&h1;
        o.z = *(unsigned*)&h2; o.w = *(unsigned*)&h3;
        ((uint4*)xh)[i] = o;
    }
    if (i < E) {
        int r = ei[E + i];
        r = min(max(r, 0), n_nodes - 1);
        atomicAdd(deg + r, 1);    // no return use -> REDG
    }
}

// ---------------------------------------------------------------------------
// 2) single-launch bucket allocation: each block scans its 256-node tile
//    locally and atomically claims a disjoint base range. Bucket order across
//    blocks is arbitrary — only disjointness matters for the CSR.
// ---------------------------------------------------------------------------
__device__ __forceinline__ int warp_incl_scan(int v, int lane) {
#pragma unroll
    for (int off = 1; off < 32; off <<= 1) {
        int u = __shfl_up_sync(0xffffffffu, v, off);
        if (lane >= off) v += u;
    }
    return v;
}

__global__ void scan_alloc_kernel(const int* __restrict__ deg,
                                  int* __restrict__ rowstart,
                                  int* __restrict__ writeptr,
                                  int* __restrict__ alloc_ctr, int n) {
    __shared__ int warp_off[SCAN_BLK / 32];
    __shared__ int sbase;
    int t = threadIdx.x;
    int lane = t & 31;
    int w = t >> 5;
    int idx = blockIdx.x * SCAN_BLK + t;
    int v = (idx < n) ? deg[idx] : 0;
    int incl = warp_incl_scan(v, lane);           // all threads active
    if (lane == 31) warp_off[w] = incl;
    __syncthreads();
    if (t < 32) {                                  // full warp active
        int s = (t < SCAN_BLK / 32) ? warp_off[t] : 0;
        int si = warp_incl_scan(s, t);
        if (t < SCAN_BLK / 32) warp_off[t] = si - s;   // exclusive warp offs
        if (t == SCAN_BLK / 32 - 1) sbase = atomicAdd(alloc_ctr, si);
    }
    __syncthreads();
    if (idx < n) {
        int start = sbase + warp_off[w] + incl - v;
        rowstart[idx] = start;
        writeptr[idx] = start;
    }
}

// ---------------------------------------------------------------------------
// 3) scatter: thread t owns CONTIGUOUS edges 8t..8t+7, vector loads,
//    8 in-flight atomic returns.
// ---------------------------------------------------------------------------
__global__ void scatter_kernel(const int* __restrict__ ei,
                               const float* __restrict__ elen,
                               const float* __restrict__ log_scale_p,
                               const float* __restrict__ fw_p,
                               const float* __restrict__ fb_p,
                               int* __restrict__ writeptr,
                               uint2* __restrict__ rec,
                               int E, int n_nodes) {
    int t = blockIdx.x * blockDim.x + threadIdx.x;
    int e0 = t * 8;
    if (e0 >= E) return;

    float scale = expf(log_scale_p[0]);
    float inv_s = 1.f / (scale + 1e-6f);
    float fw = fw_p[0];
    float fb = fb_p[0];

    int   s[8], r[8];
    float len[8];
    int   cnt;
    if (e0 + 8 <= E && (E & 3) == 0) {
        int4 sv0 = *(const int4*)(ei + e0);
        int4 sv1 = *(const int4*)(ei + e0 + 4);
        int4 rv0 = *(const int4*)(ei + E + e0);
        int4 rv1 = *(const int4*)(ei + E + e0 + 4);
        float4 lv0 = *(const float4*)(elen + e0);
        float4 lv1 = *(const float4*)(elen + e0 + 4);
        s[0]=sv0.x; s[1]=sv0.y; s[2]=sv0.z; s[3]=sv0.w;
        s[4]=sv1.x; s[5]=sv1.y; s[6]=sv1.z; s[7]=sv1.w;
        r[0]=rv0.x; r[1]=rv0.y; r[2]=rv0.z; r[3]=rv0.w;
        r[4]=rv1.x; r[5]=rv1.y; r[6]=rv1.z; r[7]=rv1.w;
        len[0]=lv0.x; len[1]=lv0.y; len[2]=lv0.z; len[3]=lv0.w;
        len[4]=lv1.x; len[5]=lv1.y; len[6]=lv1.z; len[7]=lv1.w;
        cnt = 8;
    } else {
        cnt = min(8, E - e0);
        for (int u = 0; u < cnt; u++) {
            s[u]   = ei[e0 + u];
            r[u]   = ei[E + e0 + u];
            len[u] = elen[e0 + u];
        }
    }

    float w[8];
    int   pos[8];
#pragma unroll
    for (int u = 0; u < 8; u++) {
        if (u < cnt) {
            s[u] = min(max(s[u], 0), n_nodes - 1);
            r[u] = min(max(r[u], 0), n_nodes - 1);
            float tt = fmaxf(len[u] * inv_s, 0.f);
            float d = expf(-tt * tt);
            float g = 1.f / (1.f + expf(-(len[u] * fw + fb)));
            float ww = d * g;
            if (!(ww > -3.0e38f && ww < 3.0e38f)) ww = 0.f;
            w[u] = ww;
        }
    }
#pragma unroll
    for (int u = 0; u < 8; u++) {
        if (u < cnt) pos[u] = atomicAdd(writeptr + r[u], 1);
    }
#pragma unroll
    for (int u = 0; u < 8; u++) {
        if (u < cnt) rec[pos[u]] = make_uint2((unsigned)s[u],
                                              __float_as_uint(w[u]));
    }
}

// ---------------------------------------------------------------------------
// 4) gather (fp16 x): warp per node, no smem -> full occupancy. fp32 accum,
//    writes NORMALIZED agg as fp16, then self-cleans deg[node].
// ---------------------------------------------------------------------------
__global__ void gather_kernel(const __half* __restrict__ xh,
                              const uint2* __restrict__ rec,
                              const int* __restrict__ rowstart,
                              int* __restrict__ deg,
                              __half* __restrict__ aggh, int n_nodes) {
    int wid  = (blockIdx.x * blockDim.x + threadIdx.x) >> 5;
    int lane = threadIdx.x & 31;
    if (wid >= n_nodes) return;

    int base = rowstart[wid];
    int d    = deg[wid];
    float4 acc = make_float4(0.f, 0.f, 0.f, 0.f);

    for (int j0 = 0; j0 < d; j0 += 32) {
        int n = min(32, d - j0);
        uint2 rv = make_uint2(0u, 0u);
        if (lane < n) rv = rec[base + j0 + lane];

        for (int k = 0; k < n; k += 8) {
            int   si[8];
            float wi[8];
#pragma unroll
            for (int u = 0; u < 8; u++) {
                si[u] = __shfl_sync(0xffffffffu, (int)rv.x, k + u);
                wi[u] = __uint_as_float(__shfl_sync(0xffffffffu, rv.y, k + u));
            }
            uint2 hv[8];
#pragma unroll
            for (int u = 0; u < 8; u++) {
                hv[u] = ((const uint2*)(xh + (size_t)si[u] * FEAT))[lane];
            }
#pragma unroll
            for (int u = 0; u < 8; u++) {
                float2 f0 = __half22float2(*(__half2*)&hv[u].x);
                float2 f1 = __half22float2(*(__half2*)&hv[u].y);
                acc.x = fmaf(wi[u], f0.x, acc.x);
                acc.y = fmaf(wi[u], f0.y, acc.y);
                acc.z = fmaf(wi[u], f1.x, acc.z);
                acc.w = fmaf(wi[u], f1.y, acc.w);
            }
        }
    }

    float inv = 1.f / fmaxf((float)d, 1.f);
    __half2 h0 = __floats2half2_rn(acc.x * inv, acc.y * inv);
    __half2 h1 = __floats2half2_rn(acc.z * inv, acc.w * inv);
    uint2 o;
    o.x = *(unsigned*)&h0; o.y = *(unsigned*)&h1;
    ((uint2*)(aggh + (size_t)wid * FEAT))[lane] = o;

    if (lane == 0) deg[wid] = 0;   // self-clean after the read above
}

// ---------------------------------------------------------------------------
// 5) out = x + aggh @ W  via mma.sync.m16n8k16 (f16 in, f32 accum)
// ---------------------------------------------------------------------------
#define GM 128
#define PITCH 136   // halves; 272 B, multiple of 16 B

__global__ void gemm_kernel(const float* __restrict__ x,
                            const __half* __restrict__ wt,
                            const __half* __restrict__ aggh,
                            float* __restrict__ out,
                            int n_nodes) {
    extern __shared__ __half sh[];
    __half* sA = sh;                  // GM rows * PITCH
    __half* sB = sh + GM * PITCH;     // FEAT rows * PITCH (Wt: [n][k])

    int tid = threadIdx.x;
    int lane = tid & 31;
    int wid = tid >> 5;               // 0..7
    int row0 = blockIdx.x * GM;

    for (int i = tid; i < GM * 16; i += 256) {
        int r = i >> 4;
        int c = i & 15;
        uint4 v = make_uint4(0u, 0u, 0u, 0u);
        int row = row0 + r;
        if (row < n_nodes) {
            v = ((const uint4*)(aggh + (size_t)row * FEAT))[c];
        }
        *(uint4*)(sA + r * PITCH + c * 8) = v;
    }
    for (int i = tid; i < FEAT * 16; i += 256) {
        int r = i >> 4;
        int c = i & 15;
        uint4 v = ((const uint4*)(wt + r * FEAT))[c];
        *(uint4*)(sB + r * PITCH + c * 8) = v;
    }
    __syncthreads();

    int warpRow = wid * 16;
    int g = lane >> 2;        // 0..7
    int tg = lane & 3;        // 0..3

    unsigned af[8][4];
    {
        int arow = warpRow + (lane & 15);
        int acolH = (lane >> 4) << 3;   // 0 or 8 halves
#pragma unroll
        for (int kk = 0; kk < 8; kk++) {
            unsigned addr = (unsigned)__cvta_generic_to_shared(
                sA + arow * PITCH + kk * 16 + acolH);
            asm volatile(
                "ldmatrix.sync.aligned.m8n8.x4.shared.b16 {%0,%1,%2,%3}, [%4];"
                : "=r"(af[kk][0]), "=r"(af[kk][1]),
                  "=r"(af[kk][2]), "=r"(af[kk][3])
                : "r"(addr));
        }
    }

    int r1 = row0 + warpRow + g;
    int r2 = r1 + 8;

#pragma unroll
    for (int n = 0; n < 16; n += 2) {
        float c0[4] = {0.f, 0.f, 0.f, 0.f};
        float c1[4] = {0.f, 0.f, 0.f, 0.f};
#pragma unroll
        for (int kk = 0; kk < 8; kk++) {
            int brow0 = (n << 3) + (lane & 7);
            int bcol  = (kk << 4) + (((lane >> 3) & 1) << 3);
            unsigned baddr0 = (unsigned)__cvta_generic_to_shared(
                sB + brow0 * PITCH + bcol);
            unsigned baddr1 = (unsigned)__cvta_generic_to_shared(
                sB + (brow0 + 8) * PITCH + bcol);
            unsigned b0, b1, b2, b3;
            asm volatile(
                "ldmatrix.sync.aligned.m8n8.x2.shared.b16 {%0,%1}, [%2];"
                : "=r"(b0), "=r"(b1) : "r"(baddr0));
            asm volatile(
                "ldmatrix.sync.aligned.m8n8.x2.shared.b16 {%0,%1}, [%2];"
                : "=r"(b2), "=r"(b3) : "r"(baddr1));
            asm volatile(
                "mma.sync.aligned.m16n8k16.row.col.f32.f16.f16.f32 "
                "{%0,%1,%2,%3}, {%4,%5,%6,%7}, {%8,%9}, {%0,%1,%2,%3};"
                : "+f"(c0[0]), "+f"(c0[1]), "+f"(c0[2]), "+f"(c0[3])
                : "r"(af[kk][0]), "r"(af[kk][1]), "r"(af[kk][2]), "r"(af[kk][3]),
                  "r"(b0), "r"(b1));
            asm volatile(
                "mma.sync.aligned.m16n8k16.row.col.f32.f16.f16.f32 "
                "{%0,%1,%2,%3}, {%4,%5,%6,%7}, {%8,%9}, {%0,%1,%2,%3};"
                : "+f"(c1[0]), "+f"(c1[1]), "+f"(c1[2]), "+f"(c1[3])
                : "r"(af[kk][0]), "r"(af[kk][1]), "r"(af[kk][2]), "r"(af[kk][3]),
                  "r"(b2), "r"(b3));
        }
        int col0 = (n << 3) + (tg << 1);
        int col1 = col0 + 8;
        if (r1 < n_nodes) {
            float2 xv0 = *(const float2*)(x + (size_t)r1 * FEAT + col0);
            float2 xv1 = *(const float2*)(x + (size_t)r1 * FEAT + col1);
            *(float2*)(out + (size_t)r1 * FEAT + col0) =
                make_float2(c0[0] + xv0.x, c0[1] + xv0.y);
            *(float2*)(out + (size_t)r1 * FEAT + col1) =
                make_float2(c1[0] + xv1.x, c1[1] + xv1.y);
        }
        if (r2 < n_nodes) {
            float2 xv0 = *(const float2*)(x + (size_t)r2 * FEAT + col0);
            float2 xv1 = *(const float2*)(x + (size_t)r2 * FEAT + col1);
            *(float2*)(out + (size_t)r2 * FEAT + col0) =
                make_float2(c0[2] + xv0.x, c0[3] + xv0.y);
            *(float2*)(out + (size_t)r2 * FEAT + col1) =
                make_float2(c1[2] + xv1.x, c1[3] + xv1.y);
        }
    }
}

// ---------------------------------------------------------------------------
extern "C" void kernel_launch(void* const* d_in, const int* in_sizes, int n_in,
                              void* d_out, int out_size) {
    const float* x    = (const float*)d_in[0];
    const int*   ei   = (const int*)d_in[1];
    const float* elen = (const float*)d_in[2];
    const float* W    = (const float*)d_in[3];
    const float* lsc  = (const float*)d_in[4];
    const float* fw   = (const float*)d_in[5];
    const float* fb   = (const float*)d_in[6];
    float* out = (float*)d_out;

    int n_nodes = in_sizes[0] / FEAT;
    int E       = in_sizes[2];
    if (E > MAX_EDGES) E = MAX_EDGES;

    __half* aggh;     cudaGetSymbolAddress((void**)&aggh, g_aggh);
    __half* xh;       cudaGetSymbolAddress((void**)&xh, g_xh);
    __half* wt;       cudaGetSymbolAddress((void**)&wt, g_wt);
    int*    deg;      cudaGetSymbolAddress((void**)&deg, g_deg);
    int*    rowstart; cudaGetSymbolAddress((void**)&rowstart, g_rowstart);
    int*    writeptr; cudaGetSymbolAddress((void**)&writeptr, g_writeptr);
    int*    actr;     cudaGetSymbolAddress((void**)&actr, g_alloc_ctr);
    uint2*  rec;      cudaGetSymbolAddress((void**)&rec, g_rec);

    // 1) fused prep + histogram (+ allocator reset)
    {
        int n8 = n_nodes * FEAT / 8;
        prep_hist_kernel<<<(E + 255) / 256, 256>>>(x, W, ei, xh, wt, deg,
                                                   actr, n8, E, n_nodes);
    }

    // 2) single-launch bucket allocation (atomic block-bid scan)
    {
        int nb = (n_nodes + SCAN_BLK - 1) / SCAN_BLK;   // 196
        scan_alloc_kernel<<<nb, SCAN_BLK>>>(deg, rowstart, writeptr,
                                            actr, n_nodes);
    }

    // 3) bucket scatter, 8 contiguous edges per thread
    {
        int T = (E + 7) / 8;
        scatter_kernel<<<(T + 255) / 256, 256>>>(ei, elen, lsc, fw, fb,
                                                 writeptr, rec, E, n_nodes);
    }

    // 4) gather (warp per node, full occupancy) -> fp16 agg; self-cleans deg
    {
        long long total = (long long)n_nodes * 32;
        int blocks = (int)((total + 255) / 256);
        gather_kernel<<<blocks, 256>>>(xh, rec, rowstart, deg, aggh, n_nodes);
    }

    // 5) tensor-core GEMM + residual
    {
        int smem = (GM * PITCH + FEAT * PITCH) * (int)sizeof(__half); // ~68 KB
        cudaFuncSetAttribute(gemm_kernel,
                             cudaFuncAttributeMaxDynamicSharedMemorySize, smem);
        gemm_kernel<<<(n_nodes + GM - 1) / GM, 256, smem>>>(x, wt, aggh, out,
                                                            n_nodes);
    }
}

// round 16
// speedup vs baseline: 1.1026x; 1.0416x over previous
#include <cuda_runtime.h>
#include <cuda_fp16.h>
#include <math.h>

#define MAX_NODES 50000
#define MAX_EDGES 1500000
#define FEAT 128
#define SCAN_BLK 256

// Scratch (device globals; allocation-free rule).
// g_deg is SELF-CLEANING: zero at module load; the gather kernel re-zeroes
// every entry after its (single-owner) read, so deg is zero at the start of
// every kernel_launch execution, including graph replays.
// g_alloc_ctr is reset by prep_hist_kernel (stream-ordered before the scan).
__device__ __half g_aggh[MAX_NODES * FEAT];   // fp16 normalized aggregate
__device__ __half g_xh[MAX_NODES * FEAT];     // fp16 copy of x
__device__ __half g_wt[FEAT * FEAT];          // fp16 W^T (wt[n][k] = W[k][n])
__device__ int    g_deg[MAX_NODES];
__device__ int    g_rowstart[MAX_NODES];
__device__ int    g_writeptr[MAX_NODES];
__device__ int    g_alloc_ctr;
__device__ uint2  g_rec[MAX_EDGES];           // {sender, half2(w,w) bits}

// ---------------------------------------------------------------------------
// 1) prep+hist: x -> fp16, W -> fp16 transpose, receiver histogram,
//    reset the bucket allocator. deg is already zero on entry.
// ---------------------------------------------------------------------------
__global__ void prep_hist_kernel(const float* __restrict__ x,
                                 const float* __restrict__ W,
                                 const int* __restrict__ ei,
                                 __half* __restrict__ xh,
                                 __half* __restrict__ wt,
                                 int* __restrict__ deg,
                                 int* __restrict__ alloc_ctr,
                                 int n8, int E, int n_nodes) {
    int i = blockIdx.x * blockDim.x + threadIdx.x;
    if (i == 0) *alloc_ctr = 0;
    if (i < FEAT * FEAT) {
        int n = i / FEAT, k = i % FEAT;
        wt[n * FEAT + k] = __float2half(W[k * FEAT + n]);
    }
    if (i < n8) {
        const float4* x4 = (const float4*)x;
        float4 a = x4[2 * i];
        float4 b = x4[2 * i + 1];
        __half2 h0 = __floats2half2_rn(a.x, a.y);
        __half2 h1 = __floats2half2_rn(a.z, a.w);
        __half2 h2 = __floats2half2_rn(b.x, b.y);
        __half2 h3 = __floats2half2_rn(b.z, b.w);
        uint4 o;
        o.x = *(unsigned*)&h0; o.y = *(unsigned*)&h1;
        o.z = *(unsigned*)&h2; o.w = *(unsigned*)&h3;
        ((uint4*)xh)[i] = o;
    }
    if (i < E) {
        int r = ei[E + i];
        r = min(max(r, 0), n_nodes - 1);
        atomicAdd(deg + r, 1);    // no return use -> REDG
    }
}

// ---------------------------------------------------------------------------
// 2) single-launch bucket allocation: each block scans its 256-node tile
//    locally and atomically claims a disjoint base range.
// ---------------------------------------------------------------------------
__device__ __forceinline__ int warp_incl_scan(int v, int lane) {
#pragma unroll
    for (int off = 1; off < 32; off <<= 1) {
        int u = __shfl_up_sync(0xffffffffu, v, off);
        if (lane >= off) v += u;
    }
    return v;
}

__global__ void scan_alloc_kernel(const int* __restrict__ deg,
                                  int* __restrict__ rowstart,
                                  int* __restrict__ writeptr,
                                  int* __restrict__ alloc_ctr, int n) {
    __shared__ int warp_off[SCAN_BLK / 32];
    __shared__ int sbase;
    int t = threadIdx.x;
    int lane = t & 31;
    int w = t >> 5;
    int idx = blockIdx.x * SCAN_BLK + t;
    int v = (idx < n) ? deg[idx] : 0;
    int incl = warp_incl_scan(v, lane);           // all threads active
    if (lane == 31) warp_off[w] = incl;
    __syncthreads();
    if (t < 32) {                                  // full warp active
        int s = (t < SCAN_BLK / 32) ? warp_off[t] : 0;
        int si = warp_incl_scan(s, t);
        if (t < SCAN_BLK / 32) warp_off[t] = si - s;   // exclusive warp offs
        if (t == SCAN_BLK / 32 - 1) sbase = atomicAdd(alloc_ctr, si);
    }
    __syncthreads();
    if (idx < n) {
        int start = sbase + warp_off[w] + incl - v;
        rowstart[idx] = start;
        writeptr[idx] = start;
    }
}

// ---------------------------------------------------------------------------
// 3) scatter: thread t owns CONTIGUOUS edges 8t..8t+7, vector loads,
//    8 in-flight atomic returns. Weight stored as duplicated half2.
// ---------------------------------------------------------------------------
__global__ void scatter_kernel(const int* __restrict__ ei,
                               const float* __restrict__ elen,
                               const float* __restrict__ log_scale_p,
                               const float* __restrict__ fw_p,
                               const float* __restrict__ fb_p,
                               int* __restrict__ writeptr,
                               uint2* __restrict__ rec,
                               int E, int n_nodes) {
    int t = blockIdx.x * blockDim.x + threadIdx.x;
    int e0 = t * 8;
    if (e0 >= E) return;

    float scale = expf(log_scale_p[0]);
    float inv_s = 1.f / (scale + 1e-6f);
    float fw = fw_p[0];
    float fb = fb_p[0];

    int   s[8], r[8];
    float len[8];
    int   cnt;
    if (e0 + 8 <= E && (E & 3) == 0) {
        int4 sv0 = *(const int4*)(ei + e0);
        int4 sv1 = *(const int4*)(ei + e0 + 4);
        int4 rv0 = *(const int4*)(ei + E + e0);
        int4 rv1 = *(const int4*)(ei + E + e0 + 4);
        float4 lv0 = *(const float4*)(elen + e0);
        float4 lv1 = *(const float4*)(elen + e0 + 4);
        s[0]=sv0.x; s[1]=sv0.y; s[2]=sv0.z; s[3]=sv0.w;
        s[4]=sv1.x; s[5]=sv1.y; s[6]=sv1.z; s[7]=sv1.w;
        r[0]=rv0.x; r[1]=rv0.y; r[2]=rv0.z; r[3]=rv0.w;
        r[4]=rv1.x; r[5]=rv1.y; r[6]=rv1.z; r[7]=rv1.w;
        len[0]=lv0.x; len[1]=lv0.y; len[2]=lv0.z; len[3]=lv0.w;
        len[4]=lv1.x; len[5]=lv1.y; len[6]=lv1.z; len[7]=lv1.w;
        cnt = 8;
    } else {
        cnt = min(8, E - e0);
        for (int u = 0; u < cnt; u++) {
            s[u]   = ei[e0 + u];
            r[u]   = ei[E + e0 + u];
            len[u] = elen[e0 + u];
        }
    }

    unsigned wbits[8];
    int      pos[8];
#pragma unroll
    for (int u = 0; u < 8; u++) {
        if (u < cnt) {
            s[u] = min(max(s[u], 0), n_nodes - 1);
            r[u] = min(max(r[u], 0), n_nodes - 1);
            float tt = fmaxf(len[u] * inv_s, 0.f);
            float d = expf(-tt * tt);
            float g = 1.f / (1.f + expf(-(len[u] * fw + fb)));
            float ww = d * g;
            if (!(ww > -3.0e38f && ww < 3.0e38f)) ww = 0.f;
            __half2 wh = __half2half2(__float2half(ww));
            wbits[u] = *(unsigned*)&wh;
        }
    }
#pragma unroll
    for (int u = 0; u < 8; u++) {
        if (u < cnt) pos[u] = atomicAdd(writeptr + r[u], 1);
    }
#pragma unroll
    for (int u = 0; u < 8; u++) {
        if (u < cnt) rec[pos[u]] = make_uint2((unsigned)s[u], wbits[u]);
    }
}

// ---------------------------------------------------------------------------
// 4) gather (fp16 x): warp per node, HFMA2 accumulate (no converts in the
//    inner loop). Normalization in fp32. Self-cleans deg[node].
// ---------------------------------------------------------------------------
__global__ void gather_kernel(const __half* __restrict__ xh,
                              const uint2* __restrict__ rec,
                              const int* __restrict__ rowstart,
                              int* __restrict__ deg,
                              __half* __restrict__ aggh, int n_nodes) {
    int wid  = (blockIdx.x * blockDim.x + threadIdx.x) >> 5;
    int lane = threadIdx.x & 31;
    if (wid >= n_nodes) return;

    int base = rowstart[wid];
    int d    = deg[wid];
    __half2 acc0 = __half2half2(__float2half(0.f));
    __half2 acc1 = acc0;

    for (int j0 = 0; j0 < d; j0 += 32) {
        int n = min(32, d - j0);
        uint2 rv = make_uint2(0u, 0u);
        if (lane < n) rv = rec[base + j0 + lane];

        for (int k = 0; k < n; k += 8) {
            int      si[8];
            unsigned wi[8];
#pragma unroll
            for (int u = 0; u < 8; u++) {
                si[u] = __shfl_sync(0xffffffffu, (int)rv.x, k + u);
                wi[u] = __shfl_sync(0xffffffffu, rv.y, k + u);
            }
            uint2 hv[8];
#pragma unroll
            for (int u = 0; u < 8; u++) {
                hv[u] = ((const uint2*)(xh + (size_t)si[u] * FEAT))[lane];
            }
#pragma unroll
            for (int u = 0; u < 8; u++) {
                __half2 wh = *(__half2*)&wi[u];
                acc0 = __hfma2(*(__half2*)&hv[u].x, wh, acc0);
                acc1 = __hfma2(*(__half2*)&hv[u].y, wh, acc1);
            }
        }
    }

    float inv = 1.f / fmaxf((float)d, 1.f);
    float2 f0 = __half22float2(acc0);
    float2 f1 = __half22float2(acc1);
    __half2 h0 = __floats2half2_rn(f0.x * inv, f0.y * inv);
    __half2 h1 = __floats2half2_rn(f1.x * inv, f1.y * inv);
    uint2 o;
    o.x = *(unsigned*)&h0; o.y = *(unsigned*)&h1;
    ((uint2*)(aggh + (size_t)wid * FEAT))[lane] = o;

    if (lane == 0) deg[wid] = 0;   // self-clean after the read above
}

// ---------------------------------------------------------------------------
// 5) out = x + aggh @ W  via mma.sync.m16n8k16 (f16 in, f32 accum)
// ---------------------------------------------------------------------------
#define GM 128
#define PITCH 136   // halves; 272 B, multiple of 16 B

__global__ void gemm_kernel(const float* __restrict__ x,
                            const __half* __restrict__ wt,
                            const __half* __restrict__ aggh,
                            float* __restrict__ out,
                            int n_nodes) {
    extern __shared__ __half sh[];
    __half* sA = sh;                  // GM rows * PITCH
    __half* sB = sh + GM * PITCH;     // FEAT rows * PITCH (Wt: [n][k])

    int tid = threadIdx.x;
    int lane = tid & 31;
    int wid = tid >> 5;               // 0..7
    int row0 = blockIdx.x * GM;

    for (int i = tid; i < GM * 16; i += 256) {
        int r = i >> 4;
        int c = i & 15;
        uint4 v = make_uint4(0u, 0u, 0u, 0u);
        int row = row0 + r;
        if (row < n_nodes) {
            v = ((const uint4*)(aggh + (size_t)row * FEAT))[c];
        }
        *(uint4*)(sA + r * PITCH + c * 8) = v;
    }
    for (int i = tid; i < FEAT * 16; i += 256) {
        int r = i >> 4;
        int c = i & 15;
        uint4 v = ((const uint4*)(wt + r * FEAT))[c];
        *(uint4*)(sB + r * PITCH + c * 8) = v;
    }
    __syncthreads();

    int warpRow = wid * 16;
    int g = lane >> 2;        // 0..7
    int tg = lane & 3;        // 0..3

    unsigned af[8][4];
    {
        int arow = warpRow + (lane & 15);
        int acolH = (lane >> 4) << 3;   // 0 or 8 halves
#pragma unroll
        for (int kk = 0; kk < 8; kk++) {
            unsigned addr = (unsigned)__cvta_generic_to_shared(
                sA + arow * PITCH + kk * 16 + acolH);
            asm volatile(
                "ldmatrix.sync.aligned.m8n8.x4.shared.b16 {%0,%1,%2,%3}, [%4];"
                : "=r"(af[kk][0]), "=r"(af[kk][1]),
                  "=r"(af[kk][2]), "=r"(af[kk][3])
                : "r"(addr));
        }
    }

    int r1 = row0 + warpRow + g;
    int r2 = r1 + 8;

#pragma unroll
    for (int n = 0; n < 16; n += 2) {
        float c0[4] = {0.f, 0.f, 0.f, 0.f};
        float c1[4] = {0.f, 0.f, 0.f, 0.f};
#pragma unroll
        for (int kk = 0; kk < 8; kk++) {
            int brow0 = (n << 3) + (lane & 7);
            int bcol  = (kk << 4) + (((lane >> 3) & 1) << 3);
            unsigned baddr0 = (unsigned)__cvta_generic_to_shared(
                sB + brow0 * PITCH + bcol);
            unsigned baddr1 = (unsigned)__cvta_generic_to_shared(
                sB + (brow0 + 8) * PITCH + bcol);
            unsigned b0, b1, b2, b3;
            asm volatile(
                "ldmatrix.sync.aligned.m8n8.x2.shared.b16 {%0,%1}, [%2];"
                : "=r"(b0), "=r"(b1) : "r"(baddr0));
            asm volatile(
                "ldmatrix.sync.aligned.m8n8.x2.shared.b16 {%0,%1}, [%2];"
                : "=r"(b2), "=r"(b3) : "r"(baddr1));
            asm volatile(
                "mma.sync.aligned.m16n8k16.row.col.f32.f16.f16.f32 "
                "{%0,%1,%2,%3}, {%4,%5,%6,%7}, {%8,%9}, {%0,%1,%2,%3};"
                : "+f"(c0[0]), "+f"(c0[1]), "+f"(c0[2]), "+f"(c0[3])
                : "r"(af[kk][0]), "r"(af[kk][1]), "r"(af[kk][2]), "r"(af[kk][3]),
                  "r"(b0), "r"(b1));
            asm volatile(
                "mma.sync.aligned.m16n8k16.row.col.f32.f16.f16.f32 "
                "{%0,%1,%2,%3}, {%4,%5,%6,%7}, {%8,%9}, {%0,%1,%2,%3};"
                : "+f"(c1[0]), "+f"(c1[1]), "+f"(c1[2]), "+f"(c1[3])
                : "r"(af[kk][0]), "r"(af[kk][1]), "r"(af[kk][2]), "r"(af[kk][3]),
                  "r"(b2), "r"(b3));
        }
        int col0 = (n << 3) + (tg << 1);
        int col1 = col0 + 8;
        if (r1 < n_nodes) {
            float2 xv0 = *(const float2*)(x + (size_t)r1 * FEAT + col0);
            float2 xv1 = *(const float2*)(x + (size_t)r1 * FEAT + col1);
            *(float2*)(out + (size_t)r1 * FEAT + col0) =
                make_float2(c0[0] + xv0.x, c0[1] + xv0.y);
            *(float2*)(out + (size_t)r1 * FEAT + col1) =
                make_float2(c1[0] + xv1.x, c1[1] + xv1.y);
        }
        if (r2 < n_nodes) {
            float2 xv0 = *(const float2*)(x + (size_t)r2 * FEAT + col0);
            float2 xv1 = *(const float2*)(x + (size_t)r2 * FEAT + col1);
            *(float2*)(out + (size_t)r2 * FEAT + col0) =
                make_float2(c0[2] + xv0.x, c0[3] + xv0.y);
            *(float2*)(out + (size_t)r2 * FEAT + col1) =
                make_float2(c1[2] + xv1.x, c1[3] + xv1.y);
        }
    }
}

// ---------------------------------------------------------------------------
extern "C" void kernel_launch(void* const* d_in, const int* in_sizes, int n_in,
                              void* d_out, int out_size) {
    const float* x    = (const float*)d_in[0];
    const int*   ei   = (const int*)d_in[1];
    const float* elen = (const float*)d_in[2];
    const float* W    = (const float*)d_in[3];
    const float* lsc  = (const float*)d_in[4];
    const float* fw   = (const float*)d_in[5];
    const float* fb   = (const float*)d_in[6];
    float* out = (float*)d_out;

    int n_nodes = in_sizes[0] / FEAT;
    int E       = in_sizes[2];
    if (E > MAX_EDGES) E = MAX_EDGES;

    __half* aggh;     cudaGetSymbolAddress((void**)&aggh, g_aggh);
    __half* xh;       cudaGetSymbolAddress((void**)&xh, g_xh);
    __half* wt;       cudaGetSymbolAddress((void**)&wt, g_wt);
    int*    deg;      cudaGetSymbolAddress((void**)&deg, g_deg);
    int*    rowstart; cudaGetSymbolAddress((void**)&rowstart, g_rowstart);
    int*    writeptr; cudaGetSymbolAddress((void**)&writeptr, g_writeptr);
    int*    actr;     cudaGetSymbolAddress((void**)&actr, g_alloc_ctr);
    uint2*  rec;      cudaGetSymbolAddress((void**)&rec, g_rec);

    // 1) fused prep + histogram (+ allocator reset)
    {
        int n8 = n_nodes * FEAT / 8;
        prep_hist_kernel<<<(E + 255) / 256, 256>>>(x, W, ei, xh, wt, deg,
                                                   actr, n8, E, n_nodes);
    }

    // 2) single-launch bucket allocation (atomic block-bid scan)
    {
        int nb = (n_nodes + SCAN_BLK - 1) / SCAN_BLK;   // 196
        scan_alloc_kernel<<<nb, SCAN_BLK>>>(deg, rowstart, writeptr,
                                            actr, n_nodes);
    }

    // 3) bucket scatter, 8 contiguous edges per thread
    {
        int T = (E + 7) / 8;
        scatter_kernel<<<(T + 255) / 256, 256>>>(ei, elen, lsc, fw, fb,
                                                 writeptr, rec, E, n_nodes);
    }

    // 4) gather (warp per node, HFMA2) -> fp16 agg; self-cleans deg
    {
        long long total = (long long)n_nodes * 32;
        int blocks = (int)((total + 255) / 256);
        gather_kernel<<<blocks, 256>>>(xh, rec, rowstart, deg, aggh, n_nodes);
    }

    // 5) tensor-core GEMM + residual
    {
        int smem = (GM * PITCH + FEAT * PITCH) * (int)sizeof(__half); // ~68 KB
        cudaFuncSetAttribute(gemm_kernel,
                             cudaFuncAttributeMaxDynamicSharedMemorySize, smem);
        gemm_kernel<<<(n_nodes + GM - 1) / GM, 256, smem>>>(x, wt, aggh, out,
                                                            n_nodes);
    }
}

// round 17
// speedup vs baseline: 1.1730x; 1.0639x over previous
#include <cuda_runtime.h>
#include <cuda_fp16.h>
#include <math.h>

#define MAX_NODES 50000
#define MAX_EDGES 1500000
#define FEAT 128
#define SCAN_BLK 256

// Scratch (device globals; allocation-free rule).
// g_deg is SELF-CLEANING: zero at module load; the gather kernel re-zeroes
// every entry after its (single-owner) read, so deg is zero at the start of
// every kernel_launch execution, including graph replays.
// g_alloc_ctr is reset by prep_hist_kernel (stream-ordered before the scan).
__device__ __half   g_aggh[MAX_NODES * FEAT]; // fp16 normalized aggregate
__device__ __half   g_xh[MAX_NODES * FEAT];   // fp16 copy of x
__device__ __half   g_wt[FEAT * FEAT];        // fp16 W^T (wt[n][k] = W[k][n])
__device__ int      g_deg[MAX_NODES];
__device__ int      g_rowstart[MAX_NODES];
__device__ int      g_writeptr[MAX_NODES];
__device__ int      g_alloc_ctr;
__device__ unsigned g_rec[MAX_EDGES];         // (w_fp16 << 16) | sender

// ---------------------------------------------------------------------------
// 1) prep+hist: x -> fp16, W -> fp16 transpose, receiver histogram,
//    reset the bucket allocator. deg is already zero on entry.
// ---------------------------------------------------------------------------
__global__ void prep_hist_kernel(const float* __restrict__ x,
                                 const float* __restrict__ W,
                                 const int* __restrict__ ei,
                                 __half* __restrict__ xh,
                                 __half* __restrict__ wt,
                                 int* __restrict__ deg,
                                 int* __restrict__ alloc_ctr,
                                 int n8, int E, int n_nodes) {
    int i = blockIdx.x * blockDim.x + threadIdx.x;
    if (i == 0) *alloc_ctr = 0;
    if (i < FEAT * FEAT) {
        int n = i / FEAT, k = i % FEAT;
        wt[n * FEAT + k] = __float2half(W[k * FEAT + n]);
    }
    if (i < n8) {
        const float4* x4 = (const float4*)x;
        float4 a = x4[2 * i];
        float4 b = x4[2 * i + 1];
        __half2 h0 = __floats2half2_rn(a.x, a.y);
        __half2 h1 = __floats2half2_rn(a.z, a.w);
        __half2 h2 = __floats2half2_rn(b.x, b.y);
        __half2 h3 = __floats2half2_rn(b.z, b.w);
        uint4 o;
        o.x = *(unsigned*)&h0; o.y = *(unsigned*)&h1;
        o.z = *(unsigned*)&h2; o.w = *(unsigned*)&h3;
        ((uint4*)xh)[i] = o;
    }
    if (i < E) {
        int r = ei[E + i];
        r = min(max(r, 0), n_nodes - 1);
        atomicAdd(deg + r, 1);    // no return use -> REDG
    }
}

// ---------------------------------------------------------------------------
// 2) single-launch bucket allocation: each block scans its 256-node tile
//    locally and atomically claims a disjoint base range.
// ---------------------------------------------------------------------------
__device__ __forceinline__ int warp_incl_scan(int v, int lane) {
#pragma unroll
    for (int off = 1; off < 32; off <<= 1) {
        int u = __shfl_up_sync(0xffffffffu, v, off);
        if (lane >= off) v += u;
    }
    return v;
}

__global__ void scan_alloc_kernel(const int* __restrict__ deg,
                                  int* __restrict__ rowstart,
                                  int* __restrict__ writeptr,
                                  int* __restrict__ alloc_ctr, int n) {
    __shared__ int warp_off[SCAN_BLK / 32];
    __shared__ int sbase;
    int t = threadIdx.x;
    int lane = t & 31;
    int w = t >> 5;
    int idx = blockIdx.x * SCAN_BLK + t;
    int v = (idx < n) ? deg[idx] : 0;
    int incl = warp_incl_scan(v, lane);           // all threads active
    if (lane == 31) warp_off[w] = incl;
    __syncthreads();
    if (t < 32) {                                  // full warp active
        int s = (t < SCAN_BLK / 32) ? warp_off[t] : 0;
        int si = warp_incl_scan(s, t);
        if (t < SCAN_BLK / 32) warp_off[t] = si - s;   // exclusive warp offs
        if (t == SCAN_BLK / 32 - 1) sbase = atomicAdd(alloc_ctr, si);
    }
    __syncthreads();
    if (idx < n) {
        int start = sbase + warp_off[w] + incl - v;
        rowstart[idx] = start;
        writeptr[idx] = start;
    }
}

// ---------------------------------------------------------------------------
// 3) scatter: thread t owns CONTIGUOUS edges 8t..8t+7, vector loads,
//    8 in-flight atomic returns. Record = (w_fp16 << 16) | sender.
//    Fast-math MUFU exp/div (precision ~2e-7, negligible vs fp16 weights).
// ---------------------------------------------------------------------------
__global__ void scatter_kernel(const int* __restrict__ ei,
                               const float* __restrict__ elen,
                               const float* __restrict__ log_scale_p,
                               const float* __restrict__ fw_p,
                               const float* __restrict__ fb_p,
                               int* __restrict__ writeptr,
                               unsigned* __restrict__ rec,
                               int E, int n_nodes) {
    int t = blockIdx.x * blockDim.x + threadIdx.x;
    int e0 = t * 8;
    if (e0 >= E) return;

    float scale = __expf(log_scale_p[0]);
    float inv_s = __fdividef(1.f, scale + 1e-6f);
    float fw = fw_p[0];
    float fb = fb_p[0];

    int   s[8], r[8];
    float len[8];
    int   cnt;
    if (e0 + 8 <= E && (E & 3) == 0) {
        int4 sv0 = *(const int4*)(ei + e0);
        int4 sv1 = *(const int4*)(ei + e0 + 4);
        int4 rv0 = *(const int4*)(ei + E + e0);
        int4 rv1 = *(const int4*)(ei + E + e0 + 4);
        float4 lv0 = *(const float4*)(elen + e0);
        float4 lv1 = *(const float4*)(elen + e0 + 4);
        s[0]=sv0.x; s[1]=sv0.y; s[2]=sv0.z; s[3]=sv0.w;
        s[4]=sv1.x; s[5]=sv1.y; s[6]=sv1.z; s[7]=sv1.w;
        r[0]=rv0.x; r[1]=rv0.y; r[2]=rv0.z; r[3]=rv0.w;
        r[4]=rv1.x; r[5]=rv1.y; r[6]=rv1.z; r[7]=rv1.w;
        len[0]=lv0.x; len[1]=lv0.y; len[2]=lv0.z; len[3]=lv0.w;
        len[4]=lv1.x; len[5]=lv1.y; len[6]=lv1.z; len[7]=lv1.w;
        cnt = 8;
    } else {
        cnt = min(8, E - e0);
        for (int u = 0; u < cnt; u++) {
            s[u]   = ei[e0 + u];
            r[u]   = ei[E + e0 + u];
            len[u] = elen[e0 + u];
        }
    }

    unsigned packed[8];
    int      pos[8];
#pragma unroll
    for (int u = 0; u < 8; u++) {
        if (u < cnt) {
            s[u] = min(max(s[u], 0), n_nodes - 1);
            r[u] = min(max(r[u], 0), n_nodes - 1);
            float tt = fmaxf(len[u] * inv_s, 0.f);
            float d = __expf(-tt * tt);
            float g = __fdividef(1.f, 1.f + __expf(-(len[u] * fw + fb)));
            float ww = d * g;
            if (!(ww > -3.0e38f && ww < 3.0e38f)) ww = 0.f;
            __half wh = __float2half(ww);
            packed[u] = ((unsigned)*(unsigned short*)&wh << 16) |
                        (unsigned)s[u];
        }
    }
#pragma unroll
    for (int u = 0; u < 8; u++) {
        if (u < cnt) pos[u] = atomicAdd(writeptr + r[u], 1);
    }
#pragma unroll
    for (int u = 0; u < 8; u++) {
        if (u < cnt) rec[pos[u]] = packed[u];
    }
}

// ---------------------------------------------------------------------------
// 4) gather (fp16 x): warp per node, HFMA2 accumulate; packed 32-bit records
//    (1 shfl/edge; AND + byte_perm unpack). Self-cleans deg[node].
// ---------------------------------------------------------------------------
__global__ void gather_kernel(const __half* __restrict__ xh,
                              const unsigned* __restrict__ rec,
                              const int* __restrict__ rowstart,
                              int* __restrict__ deg,
                              __half* __restrict__ aggh, int n_nodes) {
    int wid  = (blockIdx.x * blockDim.x + threadIdx.x) >> 5;
    int lane = threadIdx.x & 31;
    if (wid >= n_nodes) return;

    int base = rowstart[wid];
    int d    = deg[wid];
    __half2 acc0 = __half2half2(__float2half(0.f));
    __half2 acc1 = acc0;

    for (int j0 = 0; j0 < d; j0 += 32) {
        int n = min(32, d - j0);
        unsigned rv = 0u;                 // sender 0, weight +0.0h
        if (lane < n) rv = rec[base + j0 + lane];

        for (int k = 0; k < n; k += 8) {
            unsigned vv[8];
#pragma unroll
            for (int u = 0; u < 8; u++) {
                vv[u] = __shfl_sync(0xffffffffu, rv, k + u);
            }
            uint2 hv[8];
#pragma unroll
            for (int u = 0; u < 8; u++) {
                hv[u] = ((const uint2*)(xh +
                         (size_t)(vv[u] & 0xffffu) * FEAT))[lane];
            }
#pragma unroll
            for (int u = 0; u < 8; u++) {
                unsigned whb = __byte_perm(vv[u], 0u, 0x3232); // dup hi half
                __half2 wh = *(__half2*)&whb;
                acc0 = __hfma2(*(__half2*)&hv[u].x, wh, acc0);
                acc1 = __hfma2(*(__half2*)&hv[u].y, wh, acc1);
            }
        }
    }

    float inv = 1.f / fmaxf((float)d, 1.f);
    float2 f0 = __half22float2(acc0);
    float2 f1 = __half22float2(acc1);
    __half2 h0 = __floats2half2_rn(f0.x * inv, f0.y * inv);
    __half2 h1 = __floats2half2_rn(f1.x * inv, f1.y * inv);
    uint2 o;
    o.x = *(unsigned*)&h0; o.y = *(unsigned*)&h1;
    ((uint2*)(aggh + (size_t)wid * FEAT))[lane] = o;

    if (lane == 0) deg[wid] = 0;   // self-clean after the read above
}

// ---------------------------------------------------------------------------
// 5) out = x + aggh @ W  via mma.sync.m16n8k16 (f16 in, f32 accum)
// ---------------------------------------------------------------------------
#define GM 128
#define PITCH 136   // halves; 272 B, multiple of 16 B

__global__ void gemm_kernel(const float* __restrict__ x,
                            const __half* __restrict__ wt,
                            const __half* __restrict__ aggh,
                            float* __restrict__ out,
                            int n_nodes) {
    extern __shared__ __half sh[];
    __half* sA = sh;                  // GM rows * PITCH
    __half* sB = sh + GM * PITCH;     // FEAT rows * PITCH (Wt: [n][k])

    int tid = threadIdx.x;
    int lane = tid & 31;
    int wid = tid >> 5;               // 0..7
    int row0 = blockIdx.x * GM;

    for (int i = tid; i < GM * 16; i += 256) {
        int r = i >> 4;
        int c = i & 15;
        uint4 v = make_uint4(0u, 0u, 0u, 0u);
        int row = row0 + r;
        if (row < n_nodes) {
            v = ((const uint4*)(aggh + (size_t)row * FEAT))[c];
        }
        *(uint4*)(sA + r * PITCH + c * 8) = v;
    }
    for (int i = tid; i < FEAT * 16; i += 256) {
        int r = i >> 4;
        int c = i & 15;
        uint4 v = ((const uint4*)(wt + r * FEAT))[c];
        *(uint4*)(sB + r * PITCH + c * 8) = v;
    }
    __syncthreads();

    int warpRow = wid * 16;
    int g = lane >> 2;        // 0..7
    int tg = lane & 3;        // 0..3

    unsigned af[8][4];
    {
        int arow = warpRow + (lane & 15);
        int acolH = (lane >> 4) << 3;   // 0 or 8 halves
#pragma unroll
        for (int kk = 0; kk < 8; kk++) {
            unsigned addr = (unsigned)__cvta_generic_to_shared(
                sA + arow * PITCH + kk * 16 + acolH);
            asm volatile(
                "ldmatrix.sync.aligned.m8n8.x4.shared.b16 {%0,%1,%2,%3}, [%4];"
                : "=r"(af[kk][0]), "=r"(af[kk][1]),
                  "=r"(af[kk][2]), "=r"(af[kk][3])
                : "r"(addr));
        }
    }

    int r1 = row0 + warpRow + g;
    int r2 = r1 + 8;

#pragma unroll
    for (int n = 0; n < 16; n += 2) {
        float c0[4] = {0.f, 0.f, 0.f, 0.f};
        float c1[4] = {0.f, 0.f, 0.f, 0.f};
#pragma unroll
        for (int kk = 0; kk < 8; kk++) {
            int brow0 = (n << 3) + (lane & 7);
            int bcol  = (kk << 4) + (((lane >> 3) & 1) << 3);
            unsigned baddr0 = (unsigned)__cvta_generic_to_shared(
                sB + brow0 * PITCH + bcol);
            unsigned baddr1 = (unsigned)__cvta_generic_to_shared(
                sB + (brow0 + 8) * PITCH + bcol);
            unsigned b0, b1, b2, b3;
            asm volatile(
                "ldmatrix.sync.aligned.m8n8.x2.shared.b16 {%0,%1}, [%2];"
                : "=r"(b0), "=r"(b1) : "r"(baddr0));
            asm volatile(
                "ldmatrix.sync.aligned.m8n8.x2.shared.b16 {%0,%1}, [%2];"
                : "=r"(b2), "=r"(b3) : "r"(baddr1));
            asm volatile(
                "mma.sync.aligned.m16n8k16.row.col.f32.f16.f16.f32 "
                "{%0,%1,%2,%3}, {%4,%5,%6,%7}, {%8,%9}, {%0,%1,%2,%3};"
                : "+f"(c0[0]), "+f"(c0[1]), "+f"(c0[2]), "+f"(c0[3])
                : "r"(af[kk][0]), "r"(af[kk][1]), "r"(af[kk][2]), "r"(af[kk][3]),
                  "r"(b0), "r"(b1));
            asm volatile(
                "mma.sync.aligned.m16n8k16.row.col.f32.f16.f16.f32 "
                "{%0,%1,%2,%3}, {%4,%5,%6,%7}, {%8,%9}, {%0,%1,%2,%3};"
                : "+f"(c1[0]), "+f"(c1[1]), "+f"(c1[2]), "+f"(c1[3])
                : "r"(af[kk][0]), "r"(af[kk][1]), "r"(af[kk][2]), "r"(af[kk][3]),
                  "r"(b2), "r"(b3));
        }
        int col0 = (n << 3) + (tg << 1);
        int col1 = col0 + 8;
        if (r1 < n_nodes) {
            float2 xv0 = *(const float2*)(x + (size_t)r1 * FEAT + col0);
            float2 xv1 = *(const float2*)(x + (size_t)r1 * FEAT + col1);
            *(float2*)(out + (size_t)r1 * FEAT + col0) =
                make_float2(c0[0] + xv0.x, c0[1] + xv0.y);
            *(float2*)(out + (size_t)r1 * FEAT + col1) =
                make_float2(c1[0] + xv1.x, c1[1] + xv1.y);
        }
        if (r2 < n_nodes) {
            float2 xv0 = *(const float2*)(x + (size_t)r2 * FEAT + col0);
            float2 xv1 = *(const float2*)(x + (size_t)r2 * FEAT + col1);
            *(float2*)(out + (size_t)r2 * FEAT + col0) =
                make_float2(c0[2] + xv0.x, c0[3] + xv0.y);
            *(float2*)(out + (size_t)r2 * FEAT + col1) =
                make_float2(c1[2] + xv1.x, c1[3] + xv1.y);
        }
    }
}

// ---------------------------------------------------------------------------
extern "C" void kernel_launch(void* const* d_in, const int* in_sizes, int n_in,
                              void* d_out, int out_size) {
    const float* x    = (const float*)d_in[0];
    const int*   ei   = (const int*)d_in[1];
    const float* elen = (const float*)d_in[2];
    const float* W    = (const float*)d_in[3];
    const float* lsc  = (const float*)d_in[4];
    const float* fw   = (const float*)d_in[5];
    const float* fb   = (const float*)d_in[6];
    float* out = (float*)d_out;

    int n_nodes = in_sizes[0] / FEAT;
    int E       = in_sizes[2];
    if (E > MAX_EDGES) E = MAX_EDGES;

    __half*   aggh;     cudaGetSymbolAddress((void**)&aggh, g_aggh);
    __half*   xh;       cudaGetSymbolAddress((void**)&xh, g_xh);
    __half*   wt;       cudaGetSymbolAddress((void**)&wt, g_wt);
    int*      deg;      cudaGetSymbolAddress((void**)&deg, g_deg);
    int*      rowstart; cudaGetSymbolAddress((void**)&rowstart, g_rowstart);
    int*      writeptr; cudaGetSymbolAddress((void**)&writeptr, g_writeptr);
    int*      actr;     cudaGetSymbolAddress((void**)&actr, g_alloc_ctr);
    unsigned* rec;      cudaGetSymbolAddress((void**)&rec, g_rec);

    // 1) fused prep + histogram (+ allocator reset)
    {
        int n8 = n_nodes * FEAT / 8;
        prep_hist_kernel<<<(E + 255) / 256, 256>>>(x, W, ei, xh, wt, deg,
                                                   actr, n8, E, n_nodes);
    }

    // 2) single-launch bucket allocation (atomic block-bid scan)
    {
        int nb = (n_nodes + SCAN_BLK - 1) / SCAN_BLK;   // 196
        scan_alloc_kernel<<<nb, SCAN_BLK>>>(deg, rowstart, writeptr,
                                            actr, n_nodes);
    }

    // 3) bucket scatter, 8 contiguous edges per thread
    {
        int T = (E + 7) / 8;
        scatter_kernel<<<(T + 255) / 256, 256>>>(ei, elen, lsc, fw, fb,
                                                 writeptr, rec, E, n_nodes);
    }

    // 4) gather (warp per node, HFMA2, packed recs) -> fp16 agg
    {
        long long total = (long long)n_nodes * 32;
        int blocks = (int)((total + 255) / 256);
        gather_kernel<<<blocks, 256>>>(xh, rec, rowstart, deg, aggh, n_nodes);
    }

    // 5) tensor-core GEMM + residual
    {
        int smem = (GM * PITCH + FEAT * PITCH) * (int)sizeof(__half); // ~68 KB
        cudaFuncSetAttribute(gemm_kernel,
                             cudaFuncAttributeMaxDynamicSharedMemorySize, smem);
        gemm_kernel<<<(n_nodes + GM - 1) / GM, 256, smem>>>(x, wt, aggh, out,
                                                            n_nodes);
    }
}